// round 16
// baseline (speedup 1.0000x reference)
#include <cuda_runtime.h>
#include <math.h>
#include <stdint.h>

#define BB   64
#define SS   512
#define EE   128
#define HH   256
#define G4   1024
#define E2   512
#define NHH  4
#define HD   128
#define LL   9
#define NTOK (BB*SS)
#define VV   1970
#define VPAD 1984

// packed f32x2 helpers (sm_100+)
#define FMA2(acc, a, b) \
    asm("fma.rn.f32x2 %0, %1, %2, %0;" : "+l"(acc) : "l"(a), "l"(b))
#define ADD2(acc, a) \
    asm("add.rn.f32x2 %0, %0, %1;" : "+l"(acc) : "l"(a))
#define PACK2(dst, f) \
    asm("mov.b64 %0, {%1, %1};" : "=l"(dst) : "r"(__float_as_uint(f)))
#define PACK2AB(dst, fa, fb) \
    asm("mov.b64 %0, {%1, %2};" : "=l"(dst) : "r"(__float_as_uint(fa)), "r"(__float_as_uint(fb)))
#define UNPACK2(lo, hi, src) \
    asm("mov.b64 {%0, %1}, %2;" : "=r"(lo), "=r"(hi) : "l"(src))

// ---------------- scratch ------------------------------------------------------
__device__ float  g_vtab[(size_t)VPAD*2048];   // [v][2048]
__device__ float  g_xg[(size_t)2*SS*BB*G4];    // [d][t][b][g]  (token-major)
__device__ float  g_h[2*2*HH*BB];              // [buf][d][unit][b]
__device__ float  g_hall[(size_t)NTOK*E2];     // [token=b*S+t][512]
__device__ float  g_qkv[(size_t)NTOK*3*E2];
__device__ float  g_att[(size_t)NTOK*E2];
__device__ float  g_ao[(size_t)NTOK*E2];
__device__ float  g_em[(size_t)NTOK*LL];
__device__ unsigned int g_flags[2*64];         // per-CTA barrier flags (per dir)

#define PROJ_SMEM ((128*132 + 64*129)*4)
#define LSTM_SMEM ((4096 + 16384 + 1024 + 1024)*4)
#define ATTN_SMEM ((64*129*2 + 64*65)*4)

__device__ __forceinline__ float sigf(float x) { return 1.f / (1.f + expf(-x)); }

// ---------------- reset --------------------------------------------------------
__global__ void reset_kernel() {
    int idx = blockIdx.x * blockDim.x + threadIdx.x;
    if (idx < 2*2*HH*BB) g_h[idx] = 0.f;
    if (idx < 2*64) g_flags[idx] = 0u;
}

// ---------------- vocab projection table ---------------------------------------
__global__ void __launch_bounds__(256) vocab_proj_kernel(
    const float* __restrict__ embed,
    const float* __restrict__ w_f, const float* __restrict__ b_f,
    const float* __restrict__ w_b, const float* __restrict__ b_b)
{
    int vt = blockIdx.x;                 // 31 tiles of 64 vocab rows
    int gt = blockIdx.y;                 // 16 tiles of 128 gate rows (2 dirs)
    extern __shared__ float sm_p[];
    float* Ws = sm_p;                    // [128][132]
    float* Xs = sm_p + 128*132;          // [64][129]

    int tid = threadIdx.x;
    int r0 = gt * 128;
    int d  = (r0 >= G4) ? 1 : 0;
    const float* w    = d ? w_b : w_f;
    const float* bias = d ? b_b : b_f;
    int rloc0 = r0 - d * G4;
    int v0 = vt * 64;

    #pragma unroll
    for (int i = 0; i < 16; i++) {
        int idx4 = tid + 256 * i;
        int g  = idx4 >> 5;
        int kq = idx4 & 31;
        float4 v = *(const float4*)(w + (size_t)(rloc0 + g) * EE + kq * 4);
        *(float4*)&Ws[g * 132 + kq * 4] = v;
    }
    #pragma unroll
    for (int i = 0; i < 8; i++) {
        int idx4 = tid + 256 * i;
        int b  = idx4 >> 5;
        int eq = idx4 & 31;
        int vr = v0 + b; if (vr > VV - 1) vr = VV - 1;
        float4 v = *(const float4*)(embed + (size_t)vr * EE + eq * 4);
        Xs[b*129 + eq*4+0] = v.x; Xs[b*129 + eq*4+1] = v.y;
        Xs[b*129 + eq*4+2] = v.z; Xs[b*129 + eq*4+3] = v.w;
    }
    __syncthreads();

    int tx = tid & 15, ty = tid >> 4;
    float acc[8][4];
    #pragma unroll
    for (int i = 0; i < 8; i++)
        #pragma unroll
        for (int j = 0; j < 4; j++) acc[i][j] = 0.f;

    #pragma unroll 4
    for (int k = 0; k < EE; k++) {
        float xv[4];
        #pragma unroll
        for (int q = 0; q < 4; q++) xv[q] = Xs[(tx + 16*q) * 129 + k];
        #pragma unroll
        for (int i = 0; i < 8; i++) {
            float wv = Ws[(ty * 8 + i) * 132 + k];
            #pragma unroll
            for (int q = 0; q < 4; q++) acc[i][q] += wv * xv[q];
        }
    }

    #pragma unroll
    for (int i = 0; i < 8; i++) {
        int col = gt * 128 + ty * 8 + i;
        float bv = bias[rloc0 + ty * 8 + i];
        #pragma unroll
        for (int q = 0; q < 4; q++) {
            int vr = v0 + tx + 16 * q;
            g_vtab[(size_t)vr * 2048 + col] = acc[i][q] + bv;
        }
    }
}

// ---------------- gather: xg[d][t][b][:] = vtab[input[b][t]][d-half] -----------
__global__ void __launch_bounds__(256) gather_kernel(const int* __restrict__ inp)
{
    int warp = threadIdx.x >> 5, lane = threadIdx.x & 31;
    int token = blockIdx.x * 8 + warp;
    int b = token >> 9, t = token & 511;
    int v = inp[b * SS + t];

    const float4* src  = (const float4*)(g_vtab + (size_t)v * 2048);
    float4* dst0 = (float4*)(g_xg + ((size_t)(0 * SS + t) * BB + b) * G4);
    float4* dst1 = (float4*)(g_xg + ((size_t)(1 * SS + t) * BB + b) * G4);
    #pragma unroll
    for (int i = 0; i < 8; i++) dst0[lane + 32 * i] = src[lane + 32 * i];
    #pragma unroll
    for (int i = 0; i < 8; i++) dst1[lane + 32 * i] = src[256 + lane + 32 * i];
}

// ---------------- persistent BiLSTM: split-K, flag barrier, xg prefetch --------
// 128 CTAs (1/SM), 512 threads. Each (unit,batch) pair computed by 2 threads
// (half the k-sum each). Barrier = per-CTA flag array (parallel arrivals) with
// warp-0 ld.acquire poll. xg for step t+1 prefetched during step t.
__global__ void __launch_bounds__(512,1) lstm_kernel(
    const float* __restrict__ whh_f, const float* __restrict__ whh_b)
{
    int cta = blockIdx.x & 63;
    int d   = blockIdx.x >> 6;
    const float* w = d ? whh_b : whh_f;

    extern __shared__ float sm_l[];
    float4* Wg = (float4*)sm_l;                          // [4 units][256 k]
    float*  Hs = sm_l + 4096;                            // [256 k][64 b]
    float*  Xg = sm_l + 4096 + 16384;                    // [4 g][4 ul][64 b]
    unsigned long long* Pif = (unsigned long long*)(sm_l + 4096 + 16384 + 1024);  // [256]
    unsigned long long* Pgo = Pif + 256;                 // [256]

    int tid  = threadIdx.x;
    int b    = tid & 63;
    int ul   = (tid >> 6) & 3;
    int half = tid >> 8;                 // 0 or 1: k-range owner
    int u    = cta * 4 + ul;
    int pidx = ul * 64 + b;

    for (int i = tid; i < 1024; i += 512) {
        int uu = i >> 8, k = i & 255;
        int ug = cta * 4 + uu;
        Wg[i] = make_float4(w[(size_t)ug * HH + k],
                            w[(size_t)(256 + ug) * HH + k],
                            w[(size_t)(512 + ug) * HH + k],
                            w[(size_t)(768 + ug) * HH + k]);
    }

    float c = 0.f;

    // prefetch xg for step 0
    float4 xv;
    int p_gi = tid >> 6, p_bb = tid & 63;   // for tid<256 staging role
    if (tid < 256) {
        int tt0 = d ? (SS - 1) : 0;
        xv = *(const float4*)(g_xg +
            ((size_t)(d * SS + tt0) * BB + p_bb) * G4 + p_gi * 256 + cta * 4);
    }

    for (int t = 0; t < SS; t++) {
        int tt = d ? (SS - 1 - t) : t;
        int rbuf = t & 1;

        // A: commit prefetched xg to smem; stage h_prev (L1-bypassed)
        if (tid < 256) {
            Xg[p_gi * 256 +   0 + p_bb] = xv.x;
            Xg[p_gi * 256 +  64 + p_bb] = xv.y;
            Xg[p_gi * 256 + 128 + p_bb] = xv.z;
            Xg[p_gi * 256 + 192 + p_bb] = xv.w;
        }
        const float4* src = (const float4*)(g_h + (size_t)(rbuf * 2 + d) * HH * BB);
        float4* dst = (float4*)Hs;
        #pragma unroll
        for (int i = 0; i < 8; i++)
            dst[tid + 512 * i] = __ldcg(src + tid + 512 * i);
        __syncthreads();

        // C: init accumulators; issue prefetch for t+1 (overlaps inner loop)
        unsigned long long aif = 0ULL, ago = 0ULL;
        if (half == 0) {
            PACK2AB(aif, Xg[0 * 256 + pidx], Xg[1 * 256 + pidx]);
            PACK2AB(ago, Xg[2 * 256 + pidx], Xg[3 * 256 + pidx]);
        }
        if (t + 1 < SS && tid < 256) {
            int ttn = d ? (SS - 2 - t) : (t + 1);
            xv = *(const float4*)(g_xg +
                ((size_t)(d * SS + ttn) * BB + p_bb) * G4 + p_gi * 256 + cta * 4);
        }

        // D: inner loop (half the k range)
        int k0 = half << 7;
        const ulonglong2* wrow = (const ulonglong2*)(Wg + ul * 256) + k0;
        const float* hrow = Hs + (size_t)k0 * 64 + b;
        #pragma unroll 8
        for (int k = 0; k < 128; k++) {
            float hv = hrow[k * 64];
            unsigned long long hh; PACK2(hh, hv);
            ulonglong2 wv = wrow[k];      // lo=(wi,wf), hi=(wg,wo)
            FMA2(aif, hh, wv.x);
            FMA2(ago, hh, wv.y);
        }

        // E: split-K exchange
        if (half == 1) {
            Pif[pidx] = aif;
            Pgo[pidx] = ago;
        }
        __syncthreads();

        // F: combine + gates + state update (half 0)
        if (half == 0) {
            ADD2(aif, Pif[pidx]);
            ADD2(ago, Pgo[pidx]);

            unsigned int bi_, bf_, bg_, bo_;
            UNPACK2(bi_, bf_, aif);
            UNPACK2(bg_, bo_, ago);
            float ig = sigf(__uint_as_float(bi_));
            float fg = sigf(__uint_as_float(bf_));
            float gg = tanhf(__uint_as_float(bg_));
            float og = sigf(__uint_as_float(bo_));
            c = fg * c + ig * gg;
            float hval = og * tanhf(c);

            int wbuf = rbuf ^ 1;
            __stcg(&g_h[((size_t)(wbuf * 2 + d) * HH + u) * BB + b], hval);
            g_hall[(size_t)(b * SS + tt) * E2 + d * HH + u] = hval;
        }

        // G: flag barrier — parallel arrivals, warp-0 acquire poll
        __syncthreads();                  // h stores complete CTA-wide
        if (tid == 0) {
            asm volatile("st.release.gpu.global.u32 [%0], %1;"
                         :: "l"(&g_flags[d * 64 + cta]), "r"((unsigned)(t + 1))
                         : "memory");
        }
        if (tid < 32) {
            unsigned tgt = (unsigned)(t + 1);
            const unsigned* f0p = &g_flags[d * 64 + tid];
            const unsigned* f1p = &g_flags[d * 64 + tid + 32];
            unsigned fa, fb;
            do {
                asm volatile("ld.acquire.gpu.global.u32 %0, [%1];"
                             : "=r"(fa) : "l"(f0p) : "memory");
                asm volatile("ld.acquire.gpu.global.u32 %0, [%1];"
                             : "=r"(fb) : "l"(f1p) : "memory");
            } while (!__all_sync(0xffffffffu, fa >= tgt && fb >= tgt));
        }
        __syncthreads();
    }
}

// ---------------- SGEMM with packed f32x2: C = A @ W^T + bias ------------------
__global__ void __launch_bounds__(256) sgemm_bias(
    const float* __restrict__ A, const float* __restrict__ W,
    const float* __restrict__ bias, float* __restrict__ C,
    int M, int N, int K)
{
    __shared__ float As[16][132];
    __shared__ float Bs[16][132];
    int tid = threadIdx.x;
    int bn = blockIdx.x * 128, bm = blockIdx.y * 128;
    int tx = tid & 15, ty = tid >> 4;

    unsigned long long acc[8][4];        // [i][p]: columns (2p, 2p+1)
    #pragma unroll
    for (int i = 0; i < 8; i++)
        #pragma unroll
        for (int p = 0; p < 4; p++) acc[i][p] = 0ULL;

    for (int k0 = 0; k0 < K; k0 += 16) {
        #pragma unroll
        for (int i = 0; i < 2; i++) {
            int idx4 = tid + 256 * i;
            int row = idx4 >> 2;
            int kq  = idx4 & 3;
            float4 va = *(const float4*)(A + (size_t)(bm + row) * K + k0 + kq * 4);
            As[kq*4+0][row] = va.x; As[kq*4+1][row] = va.y;
            As[kq*4+2][row] = va.z; As[kq*4+3][row] = va.w;
            float4 vb = *(const float4*)(W + (size_t)(bn + row) * K + k0 + kq * 4);
            Bs[kq*4+0][row] = vb.x; Bs[kq*4+1][row] = vb.y;
            Bs[kq*4+2][row] = vb.z; Bs[kq*4+3][row] = vb.w;
        }
        __syncthreads();
        #pragma unroll
        for (int k = 0; k < 16; k++) {
            float a[8];
            *(float4*)&a[0] = *(float4*)&As[k][ty * 8];
            *(float4*)&a[4] = *(float4*)&As[k][ty * 8 + 4];
            ulonglong2 b01 = *(ulonglong2*)&Bs[k][tx * 8];
            ulonglong2 b23 = *(ulonglong2*)&Bs[k][tx * 8 + 4];
            #pragma unroll
            for (int i = 0; i < 8; i++) {
                unsigned long long aa; PACK2(aa, a[i]);
                FMA2(acc[i][0], aa, b01.x);
                FMA2(acc[i][1], aa, b01.y);
                FMA2(acc[i][2], aa, b23.x);
                FMA2(acc[i][3], aa, b23.y);
            }
        }
        __syncthreads();
    }

    #pragma unroll
    for (int i = 0; i < 8; i++) {
        int r = bm + ty * 8 + i;
        #pragma unroll
        for (int p = 0; p < 4; p++) {
            unsigned int lo, hi;
            UNPACK2(lo, hi, acc[i][p]);
            int cn = bn + tx * 8 + 2 * p;
            C[(size_t)r * N + cn]     = __uint_as_float(lo) + bias[cn];
            C[(size_t)r * N + cn + 1] = __uint_as_float(hi) + bias[cn + 1];
        }
    }
}

// ---------------- batch-axis attention: per (s, head) 64x64 --------------------
__global__ void __launch_bounds__(256) attn_kernel()
{
    int s = blockIdx.x, h = blockIdx.y;
    extern __shared__ float sm_a[];
    float* Qs = sm_a;                    // [64][129] (reused for V)
    float* Ks = sm_a + 64 * 129;
    float* Ss = sm_a + 2 * 64 * 129;     // [64][65]
    int tid = threadIdx.x;

    #pragma unroll
    for (int i = 0; i < 8; i++) {
        int idx4 = tid + 256 * i;
        int b  = idx4 >> 5;
        int dq = idx4 & 31;
        size_t rbase = (size_t)(b * SS + s) * (3 * E2) + h * HD + dq * 4;
        float4 q = *(const float4*)(g_qkv + rbase);
        float4 k = *(const float4*)(g_qkv + rbase + E2);
        Qs[b*129 + dq*4+0] = q.x; Qs[b*129 + dq*4+1] = q.y;
        Qs[b*129 + dq*4+2] = q.z; Qs[b*129 + dq*4+3] = q.w;
        Ks[b*129 + dq*4+0] = k.x; Ks[b*129 + dq*4+1] = k.y;
        Ks[b*129 + dq*4+2] = k.z; Ks[b*129 + dq*4+3] = k.w;
    }
    __syncthreads();

    const float scale = 0.08838834764831845f;   // 1/sqrt(128)
    #pragma unroll
    for (int e0 = 0; e0 < 16; e0++) {
        int e = tid + 256 * e0;
        int i = e >> 6, j = e & 63;
        float acc = 0.f;
        #pragma unroll 4
        for (int k = 0; k < HD; k++) acc += Qs[i*129 + k] * Ks[j*129 + k];
        Ss[i * 65 + j] = acc * scale;
    }
    __syncthreads();

    #pragma unroll
    for (int i = 0; i < 8; i++) {
        int idx4 = tid + 256 * i;
        int b  = idx4 >> 5;
        int dq = idx4 & 31;
        size_t rbase = (size_t)(b * SS + s) * (3 * E2) + h * HD + dq * 4 + 2 * E2;
        float4 v = *(const float4*)(g_qkv + rbase);
        Qs[b*129 + dq*4+0] = v.x; Qs[b*129 + dq*4+1] = v.y;
        Qs[b*129 + dq*4+2] = v.z; Qs[b*129 + dq*4+3] = v.w;
    }
    __syncthreads();
    if (tid < 64) {
        int i = tid;
        float m = -1e30f;
        #pragma unroll 4
        for (int j = 0; j < 64; j++) m = fmaxf(m, Ss[i*65 + j]);
        float sum = 0.f;
        #pragma unroll 4
        for (int j = 0; j < 64; j++) {
            float ev = expf(Ss[i*65 + j] - m);
            Ss[i*65 + j] = ev;
            sum += ev;
        }
        float inv = 1.f / sum;
        #pragma unroll 4
        for (int j = 0; j < 64; j++) Ss[i*65 + j] *= inv;
    }
    __syncthreads();

    #pragma unroll
    for (int o0 = 0; o0 < 32; o0++) {
        int idx = tid + 256 * o0;
        int i = idx >> 7, dd = idx & 127;
        float acc = 0.f;
        #pragma unroll 4
        for (int j = 0; j < 64; j++) acc += Ss[i*65 + j] * Qs[j*129 + dd];
        g_att[(size_t)(i * SS + s) * E2 + h * HD + dd] = acc;
    }
}

// ---------------- emissions: em = ao @ w_lin^T + b_lin -------------------------
__global__ void __launch_bounds__(256) em_kernel(
    const float* __restrict__ wl, const float* __restrict__ bl)
{
    __shared__ float ws[LL * E2];
    __shared__ float bs[LL];
    int tid = threadIdx.x;
    for (int i = tid; i < LL * E2; i += 256) ws[i] = wl[i];
    if (tid < LL) bs[tid] = bl[tid];
    __syncthreads();

    int warp = tid >> 5, lane = tid & 31;
    int token = blockIdx.x * 8 + warp;

    const float* arow = g_ao + (size_t)token * E2;
    float acc[LL];
    #pragma unroll
    for (int j = 0; j < LL; j++) acc[j] = 0.f;

    #pragma unroll 4
    for (int it = 0; it < E2 / 32; it++) {
        int dd = lane + 32 * it;
        float a = arow[dd];
        #pragma unroll
        for (int j = 0; j < LL; j++) acc[j] += a * ws[j * E2 + dd];
    }
    #pragma unroll
    for (int j = 0; j < LL; j++) {
        float v = acc[j];
        #pragma unroll
        for (int off = 16; off; off >>= 1)
            v += __shfl_down_sync(0xffffffffu, v, off);
        if (lane == 0) g_em[(size_t)token * LL + j] = v + bs[j];
    }
}

// ---------------- Viterbi decode: one warp per batch (float32 output) ----------
__global__ void __launch_bounds__(32) viterbi_kernel(
    const float* __restrict__ start, const float* __restrict__ endv,
    const float* __restrict__ trans, float* __restrict__ out)
{
    int b = blockIdx.x;
    int j = threadIdx.x;
    __shared__ unsigned char hist[SS * LL];

    const float* em = g_em + (size_t)b * SS * LL;

    float tr[LL];
    if (j < LL) {
        #pragma unroll
        for (int i = 0; i < LL; i++) tr[i] = trans[i * LL + j];
    }
    float score = (j < LL) ? (start[j] + em[j]) : -1e30f;

    for (int t = 1; t < SS; t++) {
        float e = (j < LL) ? em[t * LL + j] : 0.f;
        float best = -1e30f;
        int bi = 0;
        #pragma unroll
        for (int i = 0; i < LL; i++) {
            float si = __shfl_sync(0xffffffffu, score, i);
            float v = si + ((j < LL) ? tr[i] : 0.f);
            if (v > best) { best = v; bi = i; }
        }
        if (j < LL) hist[t * LL + j] = (unsigned char)bi;
        score = best + e;
    }
    if (j < LL) score += endv[j];

    float s = (j < LL) ? score : -3e30f;
    int   idx = j;
    #pragma unroll
    for (int off = 16; off; off >>= 1) {
        float so = __shfl_down_sync(0xffffffffu, s, off);
        int   io = __shfl_down_sync(0xffffffffu, idx, off);
        if (so > s || (so == s && io < idx)) { s = so; idx = io; }
    }
    int last = __shfl_sync(0xffffffffu, idx, 0);

    __syncwarp();
    if (j == 0) {
        out[b * SS + SS - 1] = (float)last;
        int tag = last;
        for (int t = SS - 1; t >= 1; t--) {
            tag = hist[t * LL + tag];
            out[b * SS + t - 1] = (float)tag;
        }
    }
}

// ---------------- launch -------------------------------------------------------
extern "C" void kernel_launch(void* const* d_in, const int* in_sizes, int n_in,
                              void* d_out, int out_size)
{
    const void *p_input=0, *p_embed=0, *p_wihf=0, *p_bf=0, *p_wihb=0, *p_bb=0;
    const void *p_whhf=0, *p_whhb=0, *p_wo=0, *p_wqkv=0, *p_bqkv=0, *p_bo=0;
    const void *p_wlin=0, *p_blin=0, *p_start=0, *p_end=0, *p_trans=0;
    int c32k = 0, c131k = 0, c262k = 0, c1k = 0, c9 = 0;
    for (int i = 0; i < n_in; i++) {
        int sz = in_sizes[i];
        const void* p = d_in[i];
        if      (sz == 252160) p_embed = p;
        else if (sz == 786432) p_wqkv  = p;
        else if (sz == 1536)   p_bqkv  = p;
        else if (sz == 512)    p_bo    = p;
        else if (sz == 4608)   p_wlin  = p;
        else if (sz == 81)     p_trans = p;
        else if (sz == 32768)  { if (c32k == 0) p_input = p; c32k++; }
        else if (sz == 131072) { if (c131k == 0) p_wihf = p; else p_wihb = p; c131k++; }
        else if (sz == 262144) { if (c262k == 0) p_whhf = p; else if (c262k == 1) p_whhb = p; else p_wo = p; c262k++; }
        else if (sz == 1024)   { if (c1k == 0) p_bf = p; else p_bb = p; c1k++; }
        else if (sz == 9)      { if (c9 == 0) p_blin = p; else if (c9 == 1) p_start = p; else p_end = p; c9++; }
    }

    const int*   inp    = (const int*)  p_input;
    const float* embed  = (const float*)p_embed;
    const float* w_ih_f = (const float*)p_wihf;
    const float* w_hh_f = (const float*)p_whhf;
    const float* b_f    = (const float*)p_bf;
    const float* w_ih_b = (const float*)p_wihb;
    const float* w_hh_b = (const float*)p_whhb;
    const float* b_b    = (const float*)p_bb;
    const float* wqkv   = (const float*)p_wqkv;
    const float* bqkv   = (const float*)p_bqkv;
    const float* wo     = (const float*)p_wo;
    const float* bo     = (const float*)p_bo;
    const float* w_lin  = (const float*)p_wlin;
    const float* b_lin  = (const float*)p_blin;
    const float* startv = (const float*)p_start;
    const float* endv   = (const float*)p_end;
    const float* transv = (const float*)p_trans;
    float* out = (float*)d_out;

    cudaFuncSetAttribute(vocab_proj_kernel, cudaFuncAttributeMaxDynamicSharedMemorySize, PROJ_SMEM);
    cudaFuncSetAttribute(lstm_kernel,       cudaFuncAttributeMaxDynamicSharedMemorySize, LSTM_SMEM);
    cudaFuncSetAttribute(attn_kernel,       cudaFuncAttributeMaxDynamicSharedMemorySize, ATTN_SMEM);

    float* g_hall_p; cudaGetSymbolAddress((void**)&g_hall_p, g_hall);
    float* g_qkv_p;  cudaGetSymbolAddress((void**)&g_qkv_p,  g_qkv);
    float* g_att_p;  cudaGetSymbolAddress((void**)&g_att_p,  g_att);
    float* g_ao_p;   cudaGetSymbolAddress((void**)&g_ao_p,   g_ao);

    reset_kernel<<<256, 256>>>();
    vocab_proj_kernel<<<dim3(31, 16), 256, PROJ_SMEM>>>(embed, w_ih_f, b_f, w_ih_b, b_b);
    gather_kernel<<<NTOK/8, 256>>>(inp);
    lstm_kernel<<<128, 512, LSTM_SMEM>>>(w_hh_f, w_hh_b);
    sgemm_bias<<<dim3(12, 256), 256>>>(g_hall_p, wqkv, bqkv, g_qkv_p, NTOK, 3*E2, E2);
    attn_kernel<<<dim3(SS, NHH), 256, ATTN_SMEM>>>();
    sgemm_bias<<<dim3(4, 256), 256>>>(g_att_p, wo, bo, g_ao_p, NTOK, E2, E2);
    em_kernel<<<NTOK/8, 256>>>(w_lin, b_lin);
    viterbi_kernel<<<BB, 32>>>(startv, endv, transv, out);
}

// round 17
// speedup vs baseline: 1.2912x; 1.2912x over previous
#include <cuda_runtime.h>
#include <math.h>
#include <stdint.h>

#define BB   64
#define SS   512
#define EE   128
#define HH   256
#define G4   1024
#define E2   512
#define NHH  4
#define HD   128
#define LL   9
#define NTOK (BB*SS)
#define VV   1970
#define VPAD 1984

// packed f32x2 helpers (sm_100+)
#define FMA2(acc, a, b) \
    asm("fma.rn.f32x2 %0, %1, %2, %0;" : "+l"(acc) : "l"(a), "l"(b))
#define ADD2(acc, a) \
    asm("add.rn.f32x2 %0, %0, %1;" : "+l"(acc) : "l"(a))
#define PACK2(dst, f) \
    asm("mov.b64 %0, {%1, %1};" : "=l"(dst) : "r"(__float_as_uint(f)))
#define PACK2AB(dst, fa, fb) \
    asm("mov.b64 %0, {%1, %2};" : "=l"(dst) : "r"(__float_as_uint(fa)), "r"(__float_as_uint(fb)))
#define UNPACK2(lo, hi, src) \
    asm("mov.b64 {%0, %1}, %2;" : "=r"(lo), "=r"(hi) : "l"(src))

// ---------------- scratch ------------------------------------------------------
__device__ float  g_vtab[(size_t)VPAD*2048];   // [v][2048]
__device__ float  g_xg[(size_t)2*SS*BB*G4];    // [d][t][b][g]  (token-major)
__device__ float  g_h[2*2*HH*BB];              // [buf][d][unit][b]
__device__ float  g_hhist[(size_t)2*SS*HH*BB]; // [d][t][u][b]  (coalesced LSTM dump)
__device__ float  g_hall[(size_t)NTOK*E2];     // [token=b*S+t][512]
__device__ float  g_qkv[(size_t)NTOK*3*E2];
__device__ float  g_att[(size_t)NTOK*E2];
__device__ float  g_ao[(size_t)NTOK*E2];
__device__ float  g_em[(size_t)NTOK*LL];
__device__ unsigned int g_bar2[2];             // per-direction barrier counters

#define PROJ_SMEM ((128*132 + 64*129)*4)
#define LSTM_SMEM ((4096 + 16384 + 1024 + 1024)*4)
#define ATTN_SMEM ((64*129*2 + 64*65)*4)

__device__ __forceinline__ float sigf(float x) { return 1.f / (1.f + expf(-x)); }

// ---------------- reset --------------------------------------------------------
__global__ void reset_kernel() {
    int idx = blockIdx.x * blockDim.x + threadIdx.x;
    if (idx < 2*2*HH*BB) g_h[idx] = 0.f;
    if (idx < 2) g_bar2[idx] = 0u;
}

// ---------------- vocab projection table ---------------------------------------
__global__ void __launch_bounds__(256) vocab_proj_kernel(
    const float* __restrict__ embed,
    const float* __restrict__ w_f, const float* __restrict__ b_f,
    const float* __restrict__ w_b, const float* __restrict__ b_b)
{
    int vt = blockIdx.x;                 // 31 tiles of 64 vocab rows
    int gt = blockIdx.y;                 // 16 tiles of 128 gate rows (2 dirs)
    extern __shared__ float sm_p[];
    float* Ws = sm_p;                    // [128][132]
    float* Xs = sm_p + 128*132;          // [64][129]

    int tid = threadIdx.x;
    int r0 = gt * 128;
    int d  = (r0 >= G4) ? 1 : 0;
    const float* w    = d ? w_b : w_f;
    const float* bias = d ? b_b : b_f;
    int rloc0 = r0 - d * G4;
    int v0 = vt * 64;

    #pragma unroll
    for (int i = 0; i < 16; i++) {
        int idx4 = tid + 256 * i;
        int g  = idx4 >> 5;
        int kq = idx4 & 31;
        float4 v = *(const float4*)(w + (size_t)(rloc0 + g) * EE + kq * 4);
        *(float4*)&Ws[g * 132 + kq * 4] = v;
    }
    #pragma unroll
    for (int i = 0; i < 8; i++) {
        int idx4 = tid + 256 * i;
        int b  = idx4 >> 5;
        int eq = idx4 & 31;
        int vr = v0 + b; if (vr > VV - 1) vr = VV - 1;
        float4 v = *(const float4*)(embed + (size_t)vr * EE + eq * 4);
        Xs[b*129 + eq*4+0] = v.x; Xs[b*129 + eq*4+1] = v.y;
        Xs[b*129 + eq*4+2] = v.z; Xs[b*129 + eq*4+3] = v.w;
    }
    __syncthreads();

    int tx = tid & 15, ty = tid >> 4;
    float acc[8][4];
    #pragma unroll
    for (int i = 0; i < 8; i++)
        #pragma unroll
        for (int j = 0; j < 4; j++) acc[i][j] = 0.f;

    #pragma unroll 4
    for (int k = 0; k < EE; k++) {
        float xv[4];
        #pragma unroll
        for (int q = 0; q < 4; q++) xv[q] = Xs[(tx + 16*q) * 129 + k];
        #pragma unroll
        for (int i = 0; i < 8; i++) {
            float wv = Ws[(ty * 8 + i) * 132 + k];
            #pragma unroll
            for (int q = 0; q < 4; q++) acc[i][q] += wv * xv[q];
        }
    }

    #pragma unroll
    for (int i = 0; i < 8; i++) {
        int col = gt * 128 + ty * 8 + i;
        float bv = bias[rloc0 + ty * 8 + i];
        #pragma unroll
        for (int q = 0; q < 4; q++) {
            int vr = v0 + tx + 16 * q;
            g_vtab[(size_t)vr * 2048 + col] = acc[i][q] + bv;
        }
    }
}

// ---------------- gather: xg[d][t][b][:] = vtab[input[b][t]][d-half] -----------
__global__ void __launch_bounds__(256) gather_kernel(const int* __restrict__ inp)
{
    int warp = threadIdx.x >> 5, lane = threadIdx.x & 31;
    int token = blockIdx.x * 8 + warp;
    int b = token >> 9, t = token & 511;
    int v = inp[b * SS + t];

    const float4* src  = (const float4*)(g_vtab + (size_t)v * 2048);
    float4* dst0 = (float4*)(g_xg + ((size_t)(0 * SS + t) * BB + b) * G4);
    float4* dst1 = (float4*)(g_xg + ((size_t)(1 * SS + t) * BB + b) * G4);
    #pragma unroll
    for (int i = 0; i < 8; i++) dst0[lane + 32 * i] = src[lane + 32 * i];
    #pragma unroll
    for (int i = 0; i < 8; i++) dst1[lane + 32 * i] = src[256 + lane + 32 * i];
}

// ---------------- persistent BiLSTM: split-K, counter barrier, xg prefetch -----
// 128 CTAs (1/SM), 512 threads. Per-direction single-counter barrier (arrive via
// red.release, spin ld.acquire on ONE line -> L2 broadcast-friendly).
// h history dumped coalesced to g_hhist; transposed to g_hall afterwards.
__global__ void __launch_bounds__(512,1) lstm_kernel(
    const float* __restrict__ whh_f, const float* __restrict__ whh_b)
{
    int cta = blockIdx.x & 63;
    int d   = blockIdx.x >> 6;
    const float* w = d ? whh_b : whh_f;

    extern __shared__ float sm_l[];
    float4* Wg = (float4*)sm_l;                          // [4 units][256 k]
    float*  Hs = sm_l + 4096;                            // [256 k][64 b]
    float*  Xg = sm_l + 4096 + 16384;                    // [4 g][4 ul][64 b]
    unsigned long long* Pif = (unsigned long long*)(sm_l + 4096 + 16384 + 1024);  // [256]
    unsigned long long* Pgo = Pif + 256;                 // [256]

    int tid  = threadIdx.x;
    int b    = tid & 63;
    int ul   = (tid >> 6) & 3;
    int half = tid >> 8;                 // 0 or 1: k-range owner
    int u    = cta * 4 + ul;
    int pidx = ul * 64 + b;

    for (int i = tid; i < 1024; i += 512) {
        int uu = i >> 8, k = i & 255;
        int ug = cta * 4 + uu;
        Wg[i] = make_float4(w[(size_t)ug * HH + k],
                            w[(size_t)(256 + ug) * HH + k],
                            w[(size_t)(512 + ug) * HH + k],
                            w[(size_t)(768 + ug) * HH + k]);
    }

    float c = 0.f;
    unsigned int* barp = &g_bar2[d];

    // prefetch xg for step 0
    float4 xv;
    int p_gi = tid >> 6, p_bb = tid & 63;
    if (tid < 256) {
        int tt0 = d ? (SS - 1) : 0;
        xv = *(const float4*)(g_xg +
            ((size_t)(d * SS + tt0) * BB + p_bb) * G4 + p_gi * 256 + cta * 4);
    }

    for (int t = 0; t < SS; t++) {
        int tt = d ? (SS - 1 - t) : t;
        int rbuf = t & 1;

        // A: commit prefetched xg; stage h_prev (L1-bypassed)
        if (tid < 256) {
            Xg[p_gi * 256 +   0 + p_bb] = xv.x;
            Xg[p_gi * 256 +  64 + p_bb] = xv.y;
            Xg[p_gi * 256 + 128 + p_bb] = xv.z;
            Xg[p_gi * 256 + 192 + p_bb] = xv.w;
        }
        const float4* src = (const float4*)(g_h + (size_t)(rbuf * 2 + d) * HH * BB);
        float4* dst = (float4*)Hs;
        #pragma unroll
        for (int i = 0; i < 8; i++)
            dst[tid + 512 * i] = __ldcg(src + tid + 512 * i);
        __syncthreads();

        // C: init accumulators; prefetch xg for t+1 (overlaps inner loop)
        unsigned long long aif = 0ULL, ago = 0ULL;
        if (half == 0) {
            PACK2AB(aif, Xg[0 * 256 + pidx], Xg[1 * 256 + pidx]);
            PACK2AB(ago, Xg[2 * 256 + pidx], Xg[3 * 256 + pidx]);
        }
        if (t + 1 < SS && tid < 256) {
            int ttn = d ? (SS - 2 - t) : (t + 1);
            xv = *(const float4*)(g_xg +
                ((size_t)(d * SS + ttn) * BB + p_bb) * G4 + p_gi * 256 + cta * 4);
        }

        // D: inner loop (half the k range)
        int k0 = half << 7;
        const ulonglong2* wrow = (const ulonglong2*)(Wg + ul * 256) + k0;
        const float* hrow = Hs + (size_t)k0 * 64 + b;
        #pragma unroll 8
        for (int k = 0; k < 128; k++) {
            float hv = hrow[k * 64];
            unsigned long long hh; PACK2(hh, hv);
            ulonglong2 wv = wrow[k];      // lo=(wi,wf), hi=(wg,wo)
            FMA2(aif, hh, wv.x);
            FMA2(ago, hh, wv.y);
        }

        // E: split-K exchange
        if (half == 1) {
            Pif[pidx] = aif;
            Pgo[pidx] = ago;
        }
        __syncthreads();

        // F: combine + gates + state update (half 0)
        if (half == 0) {
            ADD2(aif, Pif[pidx]);
            ADD2(ago, Pgo[pidx]);

            unsigned int bi_, bf_, bg_, bo_;
            UNPACK2(bi_, bf_, aif);
            UNPACK2(bg_, bo_, ago);
            float ig = sigf(__uint_as_float(bi_));
            float fg = sigf(__uint_as_float(bf_));
            float gg = tanhf(__uint_as_float(bg_));
            float og = sigf(__uint_as_float(bo_));
            c = fg * c + ig * gg;
            float hval = og * tanhf(c);

            int wbuf = rbuf ^ 1;
            __stcg(&g_h[((size_t)(wbuf * 2 + d) * HH + u) * BB + b], hval);
            // coalesced history dump: [d][t][u][b]
            __stcg(&g_hhist[(((size_t)d * SS + tt) * HH + u) * BB + b], hval);
        }

        // G: counter barrier — red.release arrive, single-line acquire spin
        __syncthreads();
        if (tid == 0) {
            asm volatile("red.release.gpu.global.add.u32 [%0], %1;"
                         :: "l"(barp), "r"(1u) : "memory");
            unsigned target = 64u * (unsigned)(t + 1);
            unsigned v;
            do {
                asm volatile("ld.acquire.gpu.global.u32 %0, [%1];"
                             : "=r"(v) : "l"(barp) : "memory");
                if (v >= target) break;
                __nanosleep(32);
            } while (1);
        }
        __syncthreads();
    }
}

// ---------------- transpose: g_hall[token][512] <- g_hhist[d][t][u][b] ---------
__global__ void __launch_bounds__(256) hall_transpose_kernel()
{
    int t = blockIdx.x, d = blockIdx.y;
    __shared__ float tile[64][65];
    int tid = threadIdx.x;

    #pragma unroll
    for (int chunk = 0; chunk < 4; chunk++) {
        int u0 = chunk * 64;
        // load 64u x 64b coalesced over b (float4)
        #pragma unroll
        for (int i = 0; i < 4; i++) {
            int pos = tid + 256 * i;          // 1024 float4 slots
            int u_l = pos >> 4, b4 = pos & 15;
            float4 v = *(const float4*)(g_hhist +
                (((size_t)d * SS + t) * HH + u0 + u_l) * BB + b4 * 4);
            tile[b4*4+0][u_l] = v.x; tile[b4*4+1][u_l] = v.y;
            tile[b4*4+2][u_l] = v.z; tile[b4*4+3][u_l] = v.w;
        }
        __syncthreads();
        // write 64b x 64u coalesced over u (float4)
        #pragma unroll
        for (int i = 0; i < 4; i++) {
            int pos = tid + 256 * i;
            int b_l = pos >> 4, u4 = pos & 15;
            float4 v;
            v.x = tile[b_l][u4*4+0]; v.y = tile[b_l][u4*4+1];
            v.z = tile[b_l][u4*4+2]; v.w = tile[b_l][u4*4+3];
            *(float4*)(g_hall + ((size_t)b_l * SS + t) * E2 + d * HH + u0 + u4 * 4) = v;
        }
        __syncthreads();
    }
}

// ---------------- SGEMM with packed f32x2: C = A @ W^T + bias ------------------
__global__ void __launch_bounds__(256) sgemm_bias(
    const float* __restrict__ A, const float* __restrict__ W,
    const float* __restrict__ bias, float* __restrict__ C,
    int M, int N, int K)
{
    __shared__ float As[16][132];
    __shared__ float Bs[16][132];
    int tid = threadIdx.x;
    int bn = blockIdx.x * 128, bm = blockIdx.y * 128;
    int tx = tid & 15, ty = tid >> 4;

    unsigned long long acc[8][4];
    #pragma unroll
    for (int i = 0; i < 8; i++)
        #pragma unroll
        for (int p = 0; p < 4; p++) acc[i][p] = 0ULL;

    for (int k0 = 0; k0 < K; k0 += 16) {
        #pragma unroll
        for (int i = 0; i < 2; i++) {
            int idx4 = tid + 256 * i;
            int row = idx4 >> 2;
            int kq  = idx4 & 3;
            float4 va = *(const float4*)(A + (size_t)(bm + row) * K + k0 + kq * 4);
            As[kq*4+0][row] = va.x; As[kq*4+1][row] = va.y;
            As[kq*4+2][row] = va.z; As[kq*4+3][row] = va.w;
            float4 vb = *(const float4*)(W + (size_t)(bn + row) * K + k0 + kq * 4);
            Bs[kq*4+0][row] = vb.x; Bs[kq*4+1][row] = vb.y;
            Bs[kq*4+2][row] = vb.z; Bs[kq*4+3][row] = vb.w;
        }
        __syncthreads();
        #pragma unroll
        for (int k = 0; k < 16; k++) {
            float a[8];
            *(float4*)&a[0] = *(float4*)&As[k][ty * 8];
            *(float4*)&a[4] = *(float4*)&As[k][ty * 8 + 4];
            ulonglong2 b01 = *(ulonglong2*)&Bs[k][tx * 8];
            ulonglong2 b23 = *(ulonglong2*)&Bs[k][tx * 8 + 4];
            #pragma unroll
            for (int i = 0; i < 8; i++) {
                unsigned long long aa; PACK2(aa, a[i]);
                FMA2(acc[i][0], aa, b01.x);
                FMA2(acc[i][1], aa, b01.y);
                FMA2(acc[i][2], aa, b23.x);
                FMA2(acc[i][3], aa, b23.y);
            }
        }
        __syncthreads();
    }

    #pragma unroll
    for (int i = 0; i < 8; i++) {
        int r = bm + ty * 8 + i;
        #pragma unroll
        for (int p = 0; p < 4; p++) {
            unsigned int lo, hi;
            UNPACK2(lo, hi, acc[i][p]);
            int cn = bn + tx * 8 + 2 * p;
            C[(size_t)r * N + cn]     = __uint_as_float(lo) + bias[cn];
            C[(size_t)r * N + cn + 1] = __uint_as_float(hi) + bias[cn + 1];
        }
    }
}

// ---------------- batch-axis attention: per (s, head) 64x64 --------------------
__global__ void __launch_bounds__(256) attn_kernel()
{
    int s = blockIdx.x, h = blockIdx.y;
    extern __shared__ float sm_a[];
    float* Qs = sm_a;                    // [64][129] (reused for V)
    float* Ks = sm_a + 64 * 129;
    float* Ss = sm_a + 2 * 64 * 129;     // [64][65]
    int tid = threadIdx.x;

    #pragma unroll
    for (int i = 0; i < 8; i++) {
        int idx4 = tid + 256 * i;
        int b  = idx4 >> 5;
        int dq = idx4 & 31;
        size_t rbase = (size_t)(b * SS + s) * (3 * E2) + h * HD + dq * 4;
        float4 q = *(const float4*)(g_qkv + rbase);
        float4 k = *(const float4*)(g_qkv + rbase + E2);
        Qs[b*129 + dq*4+0] = q.x; Qs[b*129 + dq*4+1] = q.y;
        Qs[b*129 + dq*4+2] = q.z; Qs[b*129 + dq*4+3] = q.w;
        Ks[b*129 + dq*4+0] = k.x; Ks[b*129 + dq*4+1] = k.y;
        Ks[b*129 + dq*4+2] = k.z; Ks[b*129 + dq*4+3] = k.w;
    }
    __syncthreads();

    const float scale = 0.08838834764831845f;   // 1/sqrt(128)
    #pragma unroll
    for (int e0 = 0; e0 < 16; e0++) {
        int e = tid + 256 * e0;
        int i = e >> 6, j = e & 63;
        float acc = 0.f;
        #pragma unroll 4
        for (int k = 0; k < HD; k++) acc += Qs[i*129 + k] * Ks[j*129 + k];
        Ss[i * 65 + j] = acc * scale;
    }
    __syncthreads();

    #pragma unroll
    for (int i = 0; i < 8; i++) {
        int idx4 = tid + 256 * i;
        int b  = idx4 >> 5;
        int dq = idx4 & 31;
        size_t rbase = (size_t)(b * SS + s) * (3 * E2) + h * HD + dq * 4 + 2 * E2;
        float4 v = *(const float4*)(g_qkv + rbase);
        Qs[b*129 + dq*4+0] = v.x; Qs[b*129 + dq*4+1] = v.y;
        Qs[b*129 + dq*4+2] = v.z; Qs[b*129 + dq*4+3] = v.w;
    }
    __syncthreads();
    if (tid < 64) {
        int i = tid;
        float m = -1e30f;
        #pragma unroll 4
        for (int j = 0; j < 64; j++) m = fmaxf(m, Ss[i*65 + j]);
        float sum = 0.f;
        #pragma unroll 4
        for (int j = 0; j < 64; j++) {
            float ev = expf(Ss[i*65 + j] - m);
            Ss[i*65 + j] = ev;
            sum += ev;
        }
        float inv = 1.f / sum;
        #pragma unroll 4
        for (int j = 0; j < 64; j++) Ss[i*65 + j] *= inv;
    }
    __syncthreads();

    #pragma unroll
    for (int o0 = 0; o0 < 32; o0++) {
        int idx = tid + 256 * o0;
        int i = idx >> 7, dd = idx & 127;
        float acc = 0.f;
        #pragma unroll 4
        for (int j = 0; j < 64; j++) acc += Ss[i*65 + j] * Qs[j*129 + dd];
        g_att[(size_t)(i * SS + s) * E2 + h * HD + dd] = acc;
    }
}

// ---------------- emissions: em = ao @ w_lin^T + b_lin -------------------------
__global__ void __launch_bounds__(256) em_kernel(
    const float* __restrict__ wl, const float* __restrict__ bl)
{
    __shared__ float ws[LL * E2];
    __shared__ float bs[LL];
    int tid = threadIdx.x;
    for (int i = tid; i < LL * E2; i += 256) ws[i] = wl[i];
    if (tid < LL) bs[tid] = bl[tid];
    __syncthreads();

    int warp = tid >> 5, lane = tid & 31;
    int token = blockIdx.x * 8 + warp;

    const float* arow = g_ao + (size_t)token * E2;
    float acc[LL];
    #pragma unroll
    for (int j = 0; j < LL; j++) acc[j] = 0.f;

    #pragma unroll 4
    for (int it = 0; it < E2 / 32; it++) {
        int dd = lane + 32 * it;
        float a = arow[dd];
        #pragma unroll
        for (int j = 0; j < LL; j++) acc[j] += a * ws[j * E2 + dd];
    }
    #pragma unroll
    for (int j = 0; j < LL; j++) {
        float v = acc[j];
        #pragma unroll
        for (int off = 16; off; off >>= 1)
            v += __shfl_down_sync(0xffffffffu, v, off);
        if (lane == 0) g_em[(size_t)token * LL + j] = v + bs[j];
    }
}

// ---------------- Viterbi decode: one warp per batch (float32 output) ----------
__global__ void __launch_bounds__(32) viterbi_kernel(
    const float* __restrict__ start, const float* __restrict__ endv,
    const float* __restrict__ trans, float* __restrict__ out)
{
    int b = blockIdx.x;
    int j = threadIdx.x;
    __shared__ unsigned char hist[SS * LL];

    const float* em = g_em + (size_t)b * SS * LL;

    float tr[LL];
    if (j < LL) {
        #pragma unroll
        for (int i = 0; i < LL; i++) tr[i] = trans[i * LL + j];
    }
    float score = (j < LL) ? (start[j] + em[j]) : -1e30f;

    for (int t = 1; t < SS; t++) {
        float e = (j < LL) ? em[t * LL + j] : 0.f;
        float best = -1e30f;
        int bi = 0;
        #pragma unroll
        for (int i = 0; i < LL; i++) {
            float si = __shfl_sync(0xffffffffu, score, i);
            float v = si + ((j < LL) ? tr[i] : 0.f);
            if (v > best) { best = v; bi = i; }
        }
        if (j < LL) hist[t * LL + j] = (unsigned char)bi;
        score = best + e;
    }
    if (j < LL) score += endv[j];

    float s = (j < LL) ? score : -3e30f;
    int   idx = j;
    #pragma unroll
    for (int off = 16; off; off >>= 1) {
        float so = __shfl_down_sync(0xffffffffu, s, off);
        int   io = __shfl_down_sync(0xffffffffu, idx, off);
        if (so > s || (so == s && io < idx)) { s = so; idx = io; }
    }
    int last = __shfl_sync(0xffffffffu, idx, 0);

    __syncwarp();
    if (j == 0) {
        out[b * SS + SS - 1] = (float)last;
        int tag = last;
        for (int t = SS - 1; t >= 1; t--) {
            tag = hist[t * LL + tag];
            out[b * SS + t - 1] = (float)tag;
        }
    }
}

// ---------------- launch -------------------------------------------------------
extern "C" void kernel_launch(void* const* d_in, const int* in_sizes, int n_in,
                              void* d_out, int out_size)
{
    const void *p_input=0, *p_embed=0, *p_wihf=0, *p_bf=0, *p_wihb=0, *p_bb=0;
    const void *p_whhf=0, *p_whhb=0, *p_wo=0, *p_wqkv=0, *p_bqkv=0, *p_bo=0;
    const void *p_wlin=0, *p_blin=0, *p_start=0, *p_end=0, *p_trans=0;
    int c32k = 0, c131k = 0, c262k = 0, c1k = 0, c9 = 0;
    for (int i = 0; i < n_in; i++) {
        int sz = in_sizes[i];
        const void* p = d_in[i];
        if      (sz == 252160) p_embed = p;
        else if (sz == 786432) p_wqkv  = p;
        else if (sz == 1536)   p_bqkv  = p;
        else if (sz == 512)    p_bo    = p;
        else if (sz == 4608)   p_wlin  = p;
        else if (sz == 81)     p_trans = p;
        else if (sz == 32768)  { if (c32k == 0) p_input = p; c32k++; }
        else if (sz == 131072) { if (c131k == 0) p_wihf = p; else p_wihb = p; c131k++; }
        else if (sz == 262144) { if (c262k == 0) p_whhf = p; else if (c262k == 1) p_whhb = p; else p_wo = p; c262k++; }
        else if (sz == 1024)   { if (c1k == 0) p_bf = p; else p_bb = p; c1k++; }
        else if (sz == 9)      { if (c9 == 0) p_blin = p; else if (c9 == 1) p_start = p; else p_end = p; c9++; }
    }

    const int*   inp    = (const int*)  p_input;
    const float* embed  = (const float*)p_embed;
    const float* w_ih_f = (const float*)p_wihf;
    const float* w_hh_f = (const float*)p_whhf;
    const float* b_f    = (const float*)p_bf;
    const float* w_ih_b = (const float*)p_wihb;
    const float* w_hh_b = (const float*)p_whhb;
    const float* b_b    = (const float*)p_bb;
    const float* wqkv   = (const float*)p_wqkv;
    const float* bqkv   = (const float*)p_bqkv;
    const float* wo     = (const float*)p_wo;
    const float* bo     = (const float*)p_bo;
    const float* w_lin  = (const float*)p_wlin;
    const float* b_lin  = (const float*)p_blin;
    const float* startv = (const float*)p_start;
    const float* endv   = (const float*)p_end;
    const float* transv = (const float*)p_trans;
    float* out = (float*)d_out;

    cudaFuncSetAttribute(vocab_proj_kernel, cudaFuncAttributeMaxDynamicSharedMemorySize, PROJ_SMEM);
    cudaFuncSetAttribute(lstm_kernel,       cudaFuncAttributeMaxDynamicSharedMemorySize, LSTM_SMEM);
    cudaFuncSetAttribute(attn_kernel,       cudaFuncAttributeMaxDynamicSharedMemorySize, ATTN_SMEM);

    float* g_hall_p; cudaGetSymbolAddress((void**)&g_hall_p, g_hall);
    float* g_qkv_p;  cudaGetSymbolAddress((void**)&g_qkv_p,  g_qkv);
    float* g_att_p;  cudaGetSymbolAddress((void**)&g_att_p,  g_att);
    float* g_ao_p;   cudaGetSymbolAddress((void**)&g_ao_p,   g_ao);

    reset_kernel<<<256, 256>>>();
    vocab_proj_kernel<<<dim3(31, 16), 256, PROJ_SMEM>>>(embed, w_ih_f, b_f, w_ih_b, b_b);
    gather_kernel<<<NTOK/8, 256>>>(inp);
    lstm_kernel<<<128, 512, LSTM_SMEM>>>(w_hh_f, w_hh_b);
    hall_transpose_kernel<<<dim3(SS, 2), 256>>>();
    sgemm_bias<<<dim3(12, 256), 256>>>(g_hall_p, wqkv, bqkv, g_qkv_p, NTOK, 3*E2, E2);
    attn_kernel<<<dim3(SS, NHH), 256, ATTN_SMEM>>>();
    sgemm_bias<<<dim3(4, 256), 256>>>(g_att_p, wo, bo, g_ao_p, NTOK, E2, E2);
    em_kernel<<<NTOK/8, 256>>>(w_lin, b_lin);
    viterbi_kernel<<<BB, 32>>>(startv, endv, transv, out);
}